// round 7
// baseline (speedup 1.0000x reference)
#include <cuda_runtime.h>
#include <cuda_bf16.h>
#include <stdint.h>

// ============================================================================
// VoxMLP single persistent kernel:
//   per 128-pt tile: fused trilinear gather (+on-the-fly central-diff grads)
//   -> positional encoding -> 4-layer bf16 mma.sync MLP -> Rodrigues rotation
// Output layout (float32): [0,B) = c0 ; [B,4B) = grad (B,3) ; [4B,7B) = rot
// ============================================================================

#define GD   256
#define SX   65536   // 256*256
#define SY   256

// SMEM layout. Pitches: pitch/4 mod 32 == 4 -> conflict-free LDSM/LDS/STS.
#define PW0   144   // w0t: 128 rows x 72 bf16 (k=0..63, k63 zero pad)
#define PW1   272   // w1t/w2t: 128 x 136 bf16
#define PW3   400   // w3t: 128 x 200 bf16 (k=0..191, k191 zero)
#define PBA   400   // bufA: 128 rows x 200 bf16 (cols 128..191 = feats)
#define PBB   272   // bufB: 128 rows x 136 bf16
#define OFF_W0   0
#define OFF_W1   18432
#define OFF_W2   53248
#define OFF_W3   88064
#define OFF_BUFA 139264
#define OFF_BUFB 190464
#define OFF_BIAS 225280   // 4 x 128 f32
#define OFF_WO   227328   // 128 x 3 f32
#define OFF_BO   228864   // 3 f32 (+pad)
#define OFF_STG  228880   // 128 x 3 f32 cond staging
#define SMEM_BYTES 230416

__device__ __forceinline__ void ldsm4(uint32_t& r0, uint32_t& r1,
                                      uint32_t& r2, uint32_t& r3, uint32_t a)
{
    asm volatile("ldmatrix.sync.aligned.m8n8.x4.shared.b16 {%0,%1,%2,%3}, [%4];"
                 : "=r"(r0), "=r"(r1), "=r"(r2), "=r"(r3) : "r"(a));
}

__device__ __forceinline__ void mma16(float* c,
    uint32_t a0, uint32_t a1, uint32_t a2, uint32_t a3,
    uint32_t b0, uint32_t b1)
{
    asm("mma.sync.aligned.m16n8k16.row.col.f32.bf16.bf16.f32 "
        "{%0,%1,%2,%3}, {%4,%5,%6,%7}, {%8,%9}, {%0,%1,%2,%3};"
        : "+f"(c[0]), "+f"(c[1]), "+f"(c[2]), "+f"(c[3])
        : "r"(a0), "r"(a1), "r"(a2), "r"(a3), "r"(b0), "r"(b1));
}

// 32 rows x 64 cols GEMM chunk over `ksteps` k16 steps, double-buffered frags.
__device__ __forceinline__ void gemm32x64(uint32_t smb,
    int inOff, int inPitch, int wOff, int wPitch, int ksteps,
    float (&acc)[2][8][4], int lane, int m0, int ncol0)
{
    const int l7 = lane & 7, l8 = (lane >> 3) & 1, l16 = lane >> 4;
    uint32_t aA0 = smb + inOff + (uint32_t)(m0 + l7 + 8*l8) * inPitch + 16*l16;
    uint32_t aA1 = aA0 + 16u * inPitch;
    uint32_t bA  = smb + wOff + (uint32_t)(ncol0 + l7 + 8*l16) * wPitch + 16*l8;

    uint32_t a0[2][4], a1[2][4], bb[2][4][4];
    ldsm4(a0[0][0], a0[0][1], a0[0][2], a0[0][3], aA0);
    ldsm4(a1[0][0], a1[0][1], a1[0][2], a1[0][3], aA1);
    #pragma unroll
    for (int pr = 0; pr < 4; pr++)
        ldsm4(bb[0][pr][0], bb[0][pr][1], bb[0][pr][2], bb[0][pr][3],
              bA + (uint32_t)(pr * 16) * wPitch);

    #pragma unroll
    for (int kk = 0; kk < ksteps; kk++) {
        const int cur = kk & 1, nxt = cur ^ 1;
        if (kk + 1 < ksteps) {
            aA0 += 32; aA1 += 32; bA += 32;
            ldsm4(a0[nxt][0], a0[nxt][1], a0[nxt][2], a0[nxt][3], aA0);
            ldsm4(a1[nxt][0], a1[nxt][1], a1[nxt][2], a1[nxt][3], aA1);
            #pragma unroll
            for (int pr = 0; pr < 4; pr++)
                ldsm4(bb[nxt][pr][0], bb[nxt][pr][1], bb[nxt][pr][2], bb[nxt][pr][3],
                      bA + (uint32_t)(pr * 16) * wPitch);
        }
        #pragma unroll
        for (int pr = 0; pr < 4; pr++) {
            mma16(acc[0][2*pr+0], a0[cur][0], a0[cur][1], a0[cur][2], a0[cur][3],
                  bb[cur][pr][0], bb[cur][pr][1]);
            mma16(acc[1][2*pr+0], a1[cur][0], a1[cur][1], a1[cur][2], a1[cur][3],
                  bb[cur][pr][0], bb[cur][pr][1]);
            mma16(acc[0][2*pr+1], a0[cur][0], a0[cur][1], a0[cur][2], a0[cur][3],
                  bb[cur][pr][2], bb[cur][pr][3]);
            mma16(acc[1][2*pr+1], a1[cur][0], a1[cur][1], a1[cur][2], a1[cur][3],
                  bb[cur][pr][2], bb[cur][pr][3]);
        }
    }
}

__device__ __forceinline__ void epi32x64(char* sm, int outOff, int outPitch,
    const float* bias, float (&acc)[2][8][4], int lane, int m0, int ncol0)
{
    const int g = lane >> 2, q = lane & 3;
    #pragma unroll
    for (int h = 0; h < 2; h++) {
        char* o0 = sm + outOff + (m0 + 16*h + g) * outPitch + 2*ncol0 + 4*q;
        #pragma unroll
        for (int nt = 0; nt < 8; nt++) {
            int n = ncol0 + nt*8 + 2*q;
            float bv0 = bias[n], bv1 = bias[n+1];
            float c0 = fmaxf(acc[h][nt][0] + bv0, 0.f);
            float c1 = fmaxf(acc[h][nt][1] + bv1, 0.f);
            float c2 = fmaxf(acc[h][nt][2] + bv0, 0.f);
            float c3 = fmaxf(acc[h][nt][3] + bv1, 0.f);
            uint32_t p01, p23;
            asm("cvt.rn.bf16x2.f32 %0, %1, %2;" : "=r"(p01) : "f"(c1), "f"(c0));
            asm("cvt.rn.bf16x2.f32 %0, %1, %2;" : "=r"(p23) : "f"(c3), "f"(c2));
            *(uint32_t*)(o0 + nt*16)              = p01;
            *(uint32_t*)(o0 + 8*outPitch + nt*16) = p23;
        }
    }
}

__device__ __forceinline__ void zero_acc(float (&acc)[2][8][4]) {
    #pragma unroll
    for (int h = 0; h < 2; h++)
        #pragma unroll
        for (int i = 0; i < 8; i++)
            #pragma unroll
            for (int j = 0; j < 4; j++) acc[h][i][j] = 0.f;
}

__global__ void __launch_bounds__(256, 1) voxmlp_kernel(
    const float* __restrict__ x, const float* __restrict__ grid,
    const float* __restrict__ w0, const float* __restrict__ b0,
    const float* __restrict__ w1, const float* __restrict__ b1,
    const float* __restrict__ w2, const float* __restrict__ b2,
    const float* __restrict__ w3, const float* __restrict__ b3,
    const float* __restrict__ wo, const float* __restrict__ bo,
    float* __restrict__ out, int B)
{
    extern __shared__ char sm[];
    const int t = threadIdx.x;

    // ---- load + transpose weights into SMEM (bf16), biases/wo as f32 ----
    for (int i = t; i < 128*64; i += 256) {           // w0t
        int n = i >> 6, k = i & 63;
        ((__nv_bfloat16*)(sm + OFF_W0 + n*PW0))[k] =
            (k < 63) ? __float2bfloat16(w0[k*128 + n]) : __float2bfloat16(0.f);
    }
    for (int i = t; i < 128*128; i += 256) {          // w1t, w2t
        int n = i >> 7, k = i & 127;
        ((__nv_bfloat16*)(sm + OFF_W1 + n*PW1))[k] = __float2bfloat16(w1[k*128 + n]);
        ((__nv_bfloat16*)(sm + OFF_W2 + n*PW1))[k] = __float2bfloat16(w2[k*128 + n]);
    }
    for (int i = t; i < 128*192; i += 256) {          // w3t
        int n = i / 192, k = i % 192;
        ((__nv_bfloat16*)(sm + OFF_W3 + n*PW3))[k] =
            (k < 191) ? __float2bfloat16(w3[k*128 + n]) : __float2bfloat16(0.f);
    }
    if (t < 128) {
        float* bb = (float*)(sm + OFF_BIAS);
        bb[t] = b0[t]; bb[128 + t] = b1[t]; bb[256 + t] = b2[t]; bb[384 + t] = b3[t];
        float* wos = (float*)(sm + OFF_WO);
        wos[3*t+0] = wo[3*t+0]; wos[3*t+1] = wo[3*t+1]; wos[3*t+2] = wo[3*t+2];
    }
    if (t < 3) ((float*)(sm + OFF_BO))[t] = bo[t];
    __syncthreads();

    const uint32_t smb = [&]{ uint32_t a;
        asm("{ .reg .u64 t; cvta.to.shared.u64 t, %1; cvt.u32.u64 %0, t; }"
            : "=r"(a) : "l"(sm)); return a; }();

    const int lane = t & 31, warp = t >> 5;
    const int rg = warp & 3, ch = warp >> 2;
    const int m0 = 32 * rg, ncol0 = 64 * ch;
    const int barid = rg + 1;
    const int ntiles = (B + 127) / 128;
    const float* bias = (const float*)(sm + OFF_BIAS);
    const float* wos  = (const float*)(sm + OFF_WO);
    const float* bos  = (const float*)(sm + OFF_BO);
    float* stg = (float*)(sm + OFF_STG);

    for (int tile = blockIdx.x; tile < ntiles; tile += gridDim.x) {
        int pbase = tile * 128;

        // ============ fused gather + posenc (warps 0-3; row = t) ============
        if (ch == 0) {
            int row = m0 + lane;
            int p = pbase + row;
            int pc = (p < B) ? p : 0;

            // --- point coords ---
            float xv0 = x[3*pc+0], xv1 = x[3*pc+1], xv2 = x[3*pc+2];
            if (p >= B) { xv0 = 0.f; xv1 = 0.f; xv2 = 0.f; }

            // --- voxel indices + 32 gather loads (issue early) ---
            float fx = (xv0 + 1.0f) * 127.5f;
            float fy = (xv1 + 1.0f) * 127.5f;
            float fz = (xv2 + 1.0f) * 127.5f;
            float x0f = floorf(fx), y0f = floorf(fy), z0f = floorf(fz);
            float xd = fx - x0f, yd = fy - y0f, zd = fz - z0f;
            int ix0 = min(max((int)x0f, 0), GD-1);
            int ix1 = min(max((int)x0f + 1, 0), GD-1);
            int iy0 = min(max((int)y0f, 0), GD-1);
            int iy1 = min(max((int)y0f + 1, 0), GD-1);
            int iz0 = min(max((int)z0f, 0), GD-1);
            int iz1 = min(max((int)z0f + 1, 0), GD-1);
            int pvx = max(ix0-1, 0), nxx = min(ix1+1, GD-1);
            int pvy = max(iy0-1, 0), nxy = min(iy1+1, GD-1);
            int pvz = max(iz0-1, 0), nxz = min(iz1+1, GD-1);
            int bx0 = ix0*SX, bx1 = ix1*SX;
            int by0 = iy0*SY, by1 = iy1*SY;
            int bpx = pvx*SX, bnx = nxx*SX;
            int bpy = pvy*SY, bny = nxy*SY;

            float v000 = __ldg(grid + bx0 + by0 + iz0);
            float v001 = __ldg(grid + bx0 + by0 + iz1);
            float v010 = __ldg(grid + bx0 + by1 + iz0);
            float v011 = __ldg(grid + bx0 + by1 + iz1);
            float v100 = __ldg(grid + bx1 + by0 + iz0);
            float v101 = __ldg(grid + bx1 + by0 + iz1);
            float v110 = __ldg(grid + bx1 + by1 + iz0);
            float v111 = __ldg(grid + bx1 + by1 + iz1);
            float xm00 = __ldg(grid + bpx + by0 + iz0);
            float xm01 = __ldg(grid + bpx + by0 + iz1);
            float xm10 = __ldg(grid + bpx + by1 + iz0);
            float xm11 = __ldg(grid + bpx + by1 + iz1);
            float xp00 = __ldg(grid + bnx + by0 + iz0);
            float xp01 = __ldg(grid + bnx + by0 + iz1);
            float xp10 = __ldg(grid + bnx + by1 + iz0);
            float xp11 = __ldg(grid + bnx + by1 + iz1);
            float ym00 = __ldg(grid + bx0 + bpy + iz0);
            float ym01 = __ldg(grid + bx0 + bpy + iz1);
            float ym10 = __ldg(grid + bx1 + bpy + iz0);
            float ym11 = __ldg(grid + bx1 + bpy + iz1);
            float yp00 = __ldg(grid + bx0 + bny + iz0);
            float yp01 = __ldg(grid + bx0 + bny + iz1);
            float yp10 = __ldg(grid + bx1 + bny + iz0);
            float yp11 = __ldg(grid + bx1 + bny + iz1);
            float zm00 = __ldg(grid + bx0 + by0 + pvz);
            float zm01 = __ldg(grid + bx0 + by1 + pvz);
            float zm10 = __ldg(grid + bx1 + by0 + pvz);
            float zm11 = __ldg(grid + bx1 + by1 + pvz);
            float zp00 = __ldg(grid + bx0 + by0 + nxz);
            float zp01 = __ldg(grid + bx0 + by1 + nxz);
            float zp10 = __ldg(grid + bx1 + by0 + nxz);
            float zp11 = __ldg(grid + bx1 + by1 + nxz);

            // --- posenc while loads are in flight ---
            {
                __nv_bfloat16* fr = (__nv_bfloat16*)(sm + OFF_BUFA + row * PBA + 256);
                fr[0] = __float2bfloat16(xv0);
                fr[1] = __float2bfloat16(xv1);
                fr[2] = __float2bfloat16(xv2);
                float s0 = sinf(xv0), c0v = cosf(xv0);
                float s1 = sinf(xv1), c1v = cosf(xv1);
                float s2 = sinf(xv2), c2v = cosf(xv2);
                #pragma unroll
                for (int b = 0; b < 10; b++) {
                    int f = 3 + b*6;
                    fr[f+0] = __float2bfloat16(s0);
                    fr[f+1] = __float2bfloat16(s1);
                    fr[f+2] = __float2bfloat16(s2);
                    fr[f+3] = __float2bfloat16(c0v);
                    fr[f+4] = __float2bfloat16(c1v);
                    fr[f+5] = __float2bfloat16(c2v);
                    float ns0 = 2.f*s0*c0v, nc0 = 2.f*c0v*c0v - 1.f;
                    float ns1 = 2.f*s1*c1v, nc1 = 2.f*c1v*c1v - 1.f;
                    float ns2 = 2.f*s2*c2v, nc2 = 2.f*c2v*c2v - 1.f;
                    s0 = ns0; c0v = nc0; s1 = ns1; c1v = nc1; s2 = ns2; c2v = nc2;
                }
                fr[63] = __float2bfloat16(0.f);
            }

            // --- combine gather values ---
            const float i2 = 63.75f;   // 1/(2*NDELTA)
            float dx000 = (v100 - xm00)*i2, dx001 = (v101 - xm01)*i2;
            float dx010 = (v110 - xm10)*i2, dx011 = (v111 - xm11)*i2;
            float dx100 = (xp00 - v000)*i2, dx101 = (xp01 - v001)*i2;
            float dx110 = (xp10 - v010)*i2, dx111 = (xp11 - v011)*i2;
            float dy000 = (v010 - ym00)*i2, dy001 = (v011 - ym01)*i2;
            float dy100 = (v110 - ym10)*i2, dy101 = (v111 - ym11)*i2;
            float dy010 = (yp00 - v000)*i2, dy011 = (yp01 - v001)*i2;
            float dy110 = (yp10 - v100)*i2, dy111 = (yp11 - v101)*i2;
            float dz000 = (v001 - zm00)*i2, dz010 = (v011 - zm01)*i2;
            float dz100 = (v101 - zm10)*i2, dz110 = (v111 - zm11)*i2;
            float dz001 = (zp00 - v000)*i2, dz011 = (zp01 - v010)*i2;
            float dz101 = (zp10 - v100)*i2, dz111 = (zp11 - v110)*i2;

            float xw0 = 1.0f - xd, yw0 = 1.0f - yd, zw0 = 1.0f - zd;
            float w000 = xw0*yw0*zw0, w001 = xw0*yw0*zd;
            float w010 = xw0*yd *zw0, w011 = xw0*yd *zd;
            float w100 = xd *yw0*zw0, w101 = xd *yw0*zd;
            float w110 = xd *yd *zw0, w111 = xd *yd *zd;

            float c0 = w000*v000 + w001*v001 + w010*v010 + w011*v011
                     + w100*v100 + w101*v101 + w110*v110 + w111*v111;
            float gx = w000*dx000 + w001*dx001 + w010*dx010 + w011*dx011
                     + w100*dx100 + w101*dx101 + w110*dx110 + w111*dx111;
            float gy = w000*dy000 + w001*dy001 + w010*dy010 + w011*dy011
                     + w100*dy100 + w101*dy101 + w110*dy110 + w111*dy111;
            float gz = w000*dz000 + w001*dz001 + w010*dz010 + w011*dz011
                     + w100*dz100 + w101*dz101 + w110*dz110 + w111*dz111;

            stg[3*row+0] = gx; stg[3*row+1] = gy; stg[3*row+2] = gz;
            if (p < B) {
                out[p]         = c0;
                out[B + 3*p+0] = gx;
                out[B + 3*p+1] = gy;
                out[B + 3*p+2] = gz;
            }
        }
        asm volatile("bar.sync %0, 64;" :: "r"(barid) : "memory");

        float acc[2][8][4];

        // L0: feats(64) -> h0 (bufB)
        zero_acc(acc);
        gemm32x64(smb, OFF_BUFA + 256, PBA, OFF_W0, PW0, 4, acc, lane, m0, ncol0);
        epi32x64(sm, OFF_BUFB, PBB, bias + 0, acc, lane, m0, ncol0);
        asm volatile("bar.sync %0, 64;" :: "r"(barid) : "memory");

        // L1: h0 -> h1 (bufA cols 0..127)
        zero_acc(acc);
        gemm32x64(smb, OFF_BUFB, PBB, OFF_W1, PW1, 8, acc, lane, m0, ncol0);
        epi32x64(sm, OFF_BUFA, PBA, bias + 128, acc, lane, m0, ncol0);
        asm volatile("bar.sync %0, 64;" :: "r"(barid) : "memory");

        // L2: h1 -> h2 (bufB)
        zero_acc(acc);
        gemm32x64(smb, OFF_BUFA, PBA, OFF_W2, PW1, 8, acc, lane, m0, ncol0);
        epi32x64(sm, OFF_BUFB, PBB, bias + 256, acc, lane, m0, ncol0);
        asm volatile("bar.sync %0, 64;" :: "r"(barid) : "memory");

        // L3: concat[h2 (bufB, k0..127), feats (bufA cols 128.., k128..191)]
        zero_acc(acc);
        gemm32x64(smb, OFF_BUFB, PBB, OFF_W3, PW3, 8, acc, lane, m0, ncol0);
        gemm32x64(smb, OFF_BUFA + 256, PBA, OFF_W3 + 256, PW3, 4, acc, lane, m0, ncol0);
        epi32x64(sm, OFF_BUFA, PBA, bias + 384, acc, lane, m0, ncol0);
        asm volatile("bar.sync %0, 64;" :: "r"(barid) : "memory");

        // ---- output projection + Rodrigues ----
        {
            int r  = m0 + 16*ch + (lane & 15);
            int kh = lane >> 4;             // 0: k0..63, 1: k64..127
            const uint32_t* hr = (const uint32_t*)(sm + OFF_BUFA + r * PBA) + kh*32;
            const float* wop = wos + kh * 192;
            float r0 = 0.f, r1 = 0.f, r2 = 0.f;
            #pragma unroll 8
            for (int k2 = 0; k2 < 32; k2++) {
                uint32_t u = hr[k2];
                float h0 = __bfloat162float(*(const __nv_bfloat16*)&u);
                float h1 = __bfloat162float(*((const __nv_bfloat16*)&u + 1));
                r0 += h0 * wop[6*k2+0] + h1 * wop[6*k2+3];
                r1 += h0 * wop[6*k2+1] + h1 * wop[6*k2+4];
                r2 += h0 * wop[6*k2+2] + h1 * wop[6*k2+5];
            }
            r0 += __shfl_xor_sync(0xffffffff, r0, 16);
            r1 += __shfl_xor_sync(0xffffffff, r1, 16);
            r2 += __shfl_xor_sync(0xffffffff, r2, 16);
            int p = pbase + r;
            if (kh == 0 && p < B) {
                r0 += bos[0]; r1 += bos[1]; r2 += bos[2];
                float theta = sqrtf(r0*r0 + r1*r1 + r2*r2 + 1e-12f);
                float it = 1.f / theta;
                float e0 = r0*it, e1 = r1*it, e2 = r2*it;
                float cd0 = stg[3*r+0], cd1 = stg[3*r+1], cd2 = stg[3*r+2];
                float a = sqrtf(cd0*cd0 + cd1*cd1 + cd2*cd2 + 1e-12f);
                float ia = 1.f / a;
                float v0 = cd0*ia, v1 = cd1*ia, v2 = cd2*ia;
                float ct = cosf(theta), st = sinf(theta);
                float cr0 = e1*v2 - e2*v1;
                float cr1 = e2*v0 - e0*v2;
                float cr2 = e0*v1 - e1*v0;
                float dt = e0*v0 + e1*v1 + e2*v2;
                float omc = (1.f - ct) * dt;
                out[4*B + 3*p+0] = a * (ct*v0 + st*cr0 + omc*e0);
                out[4*B + 3*p+1] = a * (ct*v1 + st*cr1 + omc*e1);
                out[4*B + 3*p+2] = a * (ct*v2 + st*cr2 + omc*e2);
            }
        }
        asm volatile("bar.sync %0, 64;" :: "r"(barid) : "memory");
    }
}

// ---------------------------------------------------------------------------
extern "C" void kernel_launch(void* const* d_in, const int* in_sizes, int n_in,
                              void* d_out, int out_size)
{
    const float* x    = (const float*)d_in[0];
    const float* grid = (const float*)d_in[1];
    const float* w0   = (const float*)d_in[2];
    const float* b0   = (const float*)d_in[3];
    const float* w1   = (const float*)d_in[4];
    const float* b1   = (const float*)d_in[5];
    const float* w2   = (const float*)d_in[6];
    const float* b2   = (const float*)d_in[7];
    const float* w3   = (const float*)d_in[8];
    const float* b3   = (const float*)d_in[9];
    const float* wo   = (const float*)d_in[10];
    const float* bo   = (const float*)d_in[11];
    float* out = (float*)d_out;
    int B = in_sizes[0] / 3;

    int nsm = 148;
    cudaDeviceGetAttribute(&nsm, cudaDevAttrMultiProcessorCount, 0);
    cudaFuncSetAttribute(voxmlp_kernel,
                         cudaFuncAttributeMaxDynamicSharedMemorySize, SMEM_BYTES);
    voxmlp_kernel<<<nsm, 256, SMEM_BYTES>>>(x, grid, w0, b0, w1, b1, w2, b2,
                                            w3, b3, wo, bo, out, B);
}

// round 8
// speedup vs baseline: 1.3046x; 1.3046x over previous
#include <cuda_runtime.h>
#include <cuda_bf16.h>
#include <stdint.h>

// ============================================================================
// VoxMLP: (1) trilinear gather of (g, grad g) with on-the-fly central diffs
//         (2) persistent bf16 mma.sync MLP (512 thr, 32x32 warp tiles,
//             double-buffered fragments) + fused Rodrigues rotation
// Output layout (float32): [0,B) = c0 ; [B,4B) = grad (B,3) ; [4B,7B) = rot
// ============================================================================

#define GD   256
#define SX   65536   // 256*256
#define SY   256

// ---------------------------------------------------------------------------
// Kernel 1: gather + gradient (known-good, ~104us)
// ---------------------------------------------------------------------------
__global__ void __launch_bounds__(256) gather_kernel(
    const float* __restrict__ x, const float* __restrict__ grid,
    float* __restrict__ out, int B)
{
    int p = blockIdx.x * blockDim.x + threadIdx.x;
    if (p >= B) return;

    float px = x[3*p+0], py = x[3*p+1], pz = x[3*p+2];
    float fx = (px + 1.0f) * 127.5f;
    float fy = (py + 1.0f) * 127.5f;
    float fz = (pz + 1.0f) * 127.5f;
    float x0f = floorf(fx), y0f = floorf(fy), z0f = floorf(fz);
    float xd = fx - x0f, yd = fy - y0f, zd = fz - z0f;

    int ix0 = min(max((int)x0f, 0), GD-1);
    int ix1 = min(max((int)x0f + 1, 0), GD-1);
    int iy0 = min(max((int)y0f, 0), GD-1);
    int iy1 = min(max((int)y0f + 1, 0), GD-1);
    int iz0 = min(max((int)z0f, 0), GD-1);
    int iz1 = min(max((int)z0f + 1, 0), GD-1);

    int pvx = max(ix0-1, 0), nxx = min(ix1+1, GD-1);
    int pvy = max(iy0-1, 0), nxy = min(iy1+1, GD-1);
    int pvz = max(iz0-1, 0), nxz = min(iz1+1, GD-1);

    int bx0 = ix0*SX, bx1 = ix1*SX;
    int by0 = iy0*SY, by1 = iy1*SY;
    int bpx = pvx*SX, bnx = nxx*SX;
    int bpy = pvy*SY, bny = nxy*SY;

    float v000 = __ldg(grid + bx0 + by0 + iz0);
    float v001 = __ldg(grid + bx0 + by0 + iz1);
    float v010 = __ldg(grid + bx0 + by1 + iz0);
    float v011 = __ldg(grid + bx0 + by1 + iz1);
    float v100 = __ldg(grid + bx1 + by0 + iz0);
    float v101 = __ldg(grid + bx1 + by0 + iz1);
    float v110 = __ldg(grid + bx1 + by1 + iz0);
    float v111 = __ldg(grid + bx1 + by1 + iz1);

    float xm00 = __ldg(grid + bpx + by0 + iz0);
    float xm01 = __ldg(grid + bpx + by0 + iz1);
    float xm10 = __ldg(grid + bpx + by1 + iz0);
    float xm11 = __ldg(grid + bpx + by1 + iz1);
    float xp00 = __ldg(grid + bnx + by0 + iz0);
    float xp01 = __ldg(grid + bnx + by0 + iz1);
    float xp10 = __ldg(grid + bnx + by1 + iz0);
    float xp11 = __ldg(grid + bnx + by1 + iz1);

    float ym00 = __ldg(grid + bx0 + bpy + iz0);
    float ym01 = __ldg(grid + bx0 + bpy + iz1);
    float ym10 = __ldg(grid + bx1 + bpy + iz0);
    float ym11 = __ldg(grid + bx1 + bpy + iz1);
    float yp00 = __ldg(grid + bx0 + bny + iz0);
    float yp01 = __ldg(grid + bx0 + bny + iz1);
    float yp10 = __ldg(grid + bx1 + bny + iz0);
    float yp11 = __ldg(grid + bx1 + bny + iz1);

    float zm00 = __ldg(grid + bx0 + by0 + pvz);
    float zm01 = __ldg(grid + bx0 + by1 + pvz);
    float zm10 = __ldg(grid + bx1 + by0 + pvz);
    float zm11 = __ldg(grid + bx1 + by1 + pvz);
    float zp00 = __ldg(grid + bx0 + by0 + nxz);
    float zp01 = __ldg(grid + bx0 + by1 + nxz);
    float zp10 = __ldg(grid + bx1 + by0 + nxz);
    float zp11 = __ldg(grid + bx1 + by1 + nxz);

    const float i2 = 63.75f;   // 1/(2*NDELTA)

    float dx000 = (v100 - xm00)*i2, dx001 = (v101 - xm01)*i2;
    float dx010 = (v110 - xm10)*i2, dx011 = (v111 - xm11)*i2;
    float dx100 = (xp00 - v000)*i2, dx101 = (xp01 - v001)*i2;
    float dx110 = (xp10 - v010)*i2, dx111 = (xp11 - v011)*i2;

    float dy000 = (v010 - ym00)*i2, dy001 = (v011 - ym01)*i2;
    float dy100 = (v110 - ym10)*i2, dy101 = (v111 - ym11)*i2;
    float dy010 = (yp00 - v000)*i2, dy011 = (yp01 - v001)*i2;
    float dy110 = (yp10 - v100)*i2, dy111 = (yp11 - v101)*i2;

    float dz000 = (v001 - zm00)*i2, dz010 = (v011 - zm01)*i2;
    float dz100 = (v101 - zm10)*i2, dz110 = (v111 - zm11)*i2;
    float dz001 = (zp00 - v000)*i2, dz011 = (zp01 - v010)*i2;
    float dz101 = (zp10 - v100)*i2, dz111 = (zp11 - v110)*i2;

    float xw0 = 1.0f - xd, yw0 = 1.0f - yd, zw0 = 1.0f - zd;
    float w000 = xw0*yw0*zw0, w001 = xw0*yw0*zd;
    float w010 = xw0*yd *zw0, w011 = xw0*yd *zd;
    float w100 = xd *yw0*zw0, w101 = xd *yw0*zd;
    float w110 = xd *yd *zw0, w111 = xd *yd *zd;

    float c0 = w000*v000 + w001*v001 + w010*v010 + w011*v011
             + w100*v100 + w101*v101 + w110*v110 + w111*v111;
    float gx = w000*dx000 + w001*dx001 + w010*dx010 + w011*dx011
             + w100*dx100 + w101*dx101 + w110*dx110 + w111*dx111;
    float gy = w000*dy000 + w001*dy001 + w010*dy010 + w011*dy011
             + w100*dy100 + w101*dy101 + w110*dy110 + w111*dy111;
    float gz = w000*dz000 + w001*dz001 + w010*dz010 + w011*dz011
             + w100*dz100 + w101*dz101 + w110*dz110 + w111*dz111;

    out[p]         = c0;
    out[B + 3*p+0] = gx;
    out[B + 3*p+1] = gy;
    out[B + 3*p+2] = gz;
}

// ---------------------------------------------------------------------------
// Kernel 2: persistent bf16 MMA MLP + Rodrigues (512 threads)
// Warp w: rg = w&3 (rows 32rg..32rg+31), ch = w>>2 (cols 32ch..32ch+31).
// Named barrier (rg+1) over the 4 warps (128 threads) of one row-group.
// Pitches: pitch/4 mod 32 == 4 -> conflict-free LDSM/LDS/STS.
// ---------------------------------------------------------------------------
#define PW0   144   // w0t: 128 rows x 72 bf16 (k=0..63, k63 zero pad)
#define PW1   272   // w1t/w2t: 128 x 136 bf16
#define PW3   400   // w3t: 128 x 200 bf16 (k=0..191, k191 zero)
#define PBA   400   // bufA: 128 rows x 200 bf16 (cols 128..191 = feats)
#define PBB   272   // bufB: 128 rows x 136 bf16
#define OFF_W0   0
#define OFF_W1   18432
#define OFF_W2   53248
#define OFF_W3   88064
#define OFF_BUFA 139264
#define OFF_BUFB 190464
#define OFF_BIAS 225280   // 4 x 128 f32
#define OFF_WO   227328   // 128 x 3 f32
#define OFF_BO   228864   // 3 f32
#define SMEM_BYTES 228880

__device__ __forceinline__ void ldsm4(uint32_t& r0, uint32_t& r1,
                                      uint32_t& r2, uint32_t& r3, uint32_t a)
{
    asm volatile("ldmatrix.sync.aligned.m8n8.x4.shared.b16 {%0,%1,%2,%3}, [%4];"
                 : "=r"(r0), "=r"(r1), "=r"(r2), "=r"(r3) : "r"(a));
}

__device__ __forceinline__ void mma16(float* c,
    uint32_t a0, uint32_t a1, uint32_t a2, uint32_t a3,
    uint32_t b0, uint32_t b1)
{
    asm("mma.sync.aligned.m16n8k16.row.col.f32.bf16.bf16.f32 "
        "{%0,%1,%2,%3}, {%4,%5,%6,%7}, {%8,%9}, {%0,%1,%2,%3};"
        : "+f"(c[0]), "+f"(c[1]), "+f"(c[2]), "+f"(c[3])
        : "r"(a0), "r"(a1), "r"(a2), "r"(a3), "r"(b0), "r"(b1));
}

// 32 rows x 32 cols GEMM chunk over `ksteps` k16 steps, double-buffered frags.
__device__ __forceinline__ void gemm32x32(uint32_t smb,
    int inOff, int inPitch, int wOff, int wPitch, int ksteps,
    float (&acc)[2][4][4], int lane, int m0, int ncol0)
{
    const int l7 = lane & 7, l8 = (lane >> 3) & 1, l16 = lane >> 4;
    uint32_t aA0 = smb + inOff + (uint32_t)(m0 + l7 + 8*l8) * inPitch + 16*l16;
    uint32_t aA1 = aA0 + 16u * inPitch;
    uint32_t bA  = smb + wOff + (uint32_t)(ncol0 + l7 + 8*l16) * wPitch + 16*l8;

    uint32_t a0[2][4], a1[2][4], bb[2][2][4];
    ldsm4(a0[0][0], a0[0][1], a0[0][2], a0[0][3], aA0);
    ldsm4(a1[0][0], a1[0][1], a1[0][2], a1[0][3], aA1);
    #pragma unroll
    for (int pr = 0; pr < 2; pr++)
        ldsm4(bb[0][pr][0], bb[0][pr][1], bb[0][pr][2], bb[0][pr][3],
              bA + (uint32_t)(pr * 16) * wPitch);

    #pragma unroll
    for (int kk = 0; kk < ksteps; kk++) {
        const int cur = kk & 1, nxt = cur ^ 1;
        if (kk + 1 < ksteps) {
            aA0 += 32; aA1 += 32; bA += 32;
            ldsm4(a0[nxt][0], a0[nxt][1], a0[nxt][2], a0[nxt][3], aA0);
            ldsm4(a1[nxt][0], a1[nxt][1], a1[nxt][2], a1[nxt][3], aA1);
            #pragma unroll
            for (int pr = 0; pr < 2; pr++)
                ldsm4(bb[nxt][pr][0], bb[nxt][pr][1], bb[nxt][pr][2], bb[nxt][pr][3],
                      bA + (uint32_t)(pr * 16) * wPitch);
        }
        #pragma unroll
        for (int pr = 0; pr < 2; pr++) {
            mma16(acc[0][2*pr+0], a0[cur][0], a0[cur][1], a0[cur][2], a0[cur][3],
                  bb[cur][pr][0], bb[cur][pr][1]);
            mma16(acc[1][2*pr+0], a1[cur][0], a1[cur][1], a1[cur][2], a1[cur][3],
                  bb[cur][pr][0], bb[cur][pr][1]);
            mma16(acc[0][2*pr+1], a0[cur][0], a0[cur][1], a0[cur][2], a0[cur][3],
                  bb[cur][pr][2], bb[cur][pr][3]);
            mma16(acc[1][2*pr+1], a1[cur][0], a1[cur][1], a1[cur][2], a1[cur][3],
                  bb[cur][pr][2], bb[cur][pr][3]);
        }
    }
}

__device__ __forceinline__ void epi32x32(char* sm, int outOff, int outPitch,
    const float* bias, float (&acc)[2][4][4], int lane, int m0, int ncol0)
{
    const int g = lane >> 2, q = lane & 3;
    #pragma unroll
    for (int h = 0; h < 2; h++) {
        char* o0 = sm + outOff + (m0 + 16*h + g) * outPitch + 2*ncol0 + 4*q;
        #pragma unroll
        for (int nt = 0; nt < 4; nt++) {
            int n = ncol0 + nt*8 + 2*q;
            float bv0 = bias[n], bv1 = bias[n+1];
            float c0 = fmaxf(acc[h][nt][0] + bv0, 0.f);
            float c1 = fmaxf(acc[h][nt][1] + bv1, 0.f);
            float c2 = fmaxf(acc[h][nt][2] + bv0, 0.f);
            float c3 = fmaxf(acc[h][nt][3] + bv1, 0.f);
            uint32_t p01, p23;
            asm("cvt.rn.bf16x2.f32 %0, %1, %2;" : "=r"(p01) : "f"(c1), "f"(c0));
            asm("cvt.rn.bf16x2.f32 %0, %1, %2;" : "=r"(p23) : "f"(c3), "f"(c2));
            *(uint32_t*)(o0 + nt*16)              = p01;
            *(uint32_t*)(o0 + 8*outPitch + nt*16) = p23;
        }
    }
}

__device__ __forceinline__ void zero_acc(float (&acc)[2][4][4]) {
    #pragma unroll
    for (int h = 0; h < 2; h++)
        #pragma unroll
        for (int i = 0; i < 4; i++)
            #pragma unroll
            for (int j = 0; j < 4; j++) acc[h][i][j] = 0.f;
}

__global__ void __launch_bounds__(512, 1) mlp_kernel(
    const float* __restrict__ x,
    const float* __restrict__ w0, const float* __restrict__ b0,
    const float* __restrict__ w1, const float* __restrict__ b1,
    const float* __restrict__ w2, const float* __restrict__ b2,
    const float* __restrict__ w3, const float* __restrict__ b3,
    const float* __restrict__ wo, const float* __restrict__ bo,
    float* __restrict__ out, int B)
{
    extern __shared__ char sm[];
    const int t = threadIdx.x;

    // ---- load + transpose weights into SMEM (bf16), biases/wo as f32 ----
    for (int i = t; i < 128*64; i += 512) {           // w0t
        int n = i >> 6, k = i & 63;
        ((__nv_bfloat16*)(sm + OFF_W0 + n*PW0))[k] =
            (k < 63) ? __float2bfloat16(w0[k*128 + n]) : __float2bfloat16(0.f);
    }
    for (int i = t; i < 128*128; i += 512) {          // w1t, w2t
        int n = i >> 7, k = i & 127;
        ((__nv_bfloat16*)(sm + OFF_W1 + n*PW1))[k] = __float2bfloat16(w1[k*128 + n]);
        ((__nv_bfloat16*)(sm + OFF_W2 + n*PW1))[k] = __float2bfloat16(w2[k*128 + n]);
    }
    for (int i = t; i < 128*192; i += 512) {          // w3t
        int n = i / 192, k = i % 192;
        ((__nv_bfloat16*)(sm + OFF_W3 + n*PW3))[k] =
            (k < 191) ? __float2bfloat16(w3[k*128 + n]) : __float2bfloat16(0.f);
    }
    if (t < 128) {
        float* bb = (float*)(sm + OFF_BIAS);
        bb[t] = b0[t]; bb[128 + t] = b1[t]; bb[256 + t] = b2[t]; bb[384 + t] = b3[t];
        float* wos = (float*)(sm + OFF_WO);
        wos[3*t+0] = wo[3*t+0]; wos[3*t+1] = wo[3*t+1]; wos[3*t+2] = wo[3*t+2];
    }
    if (t < 3) ((float*)(sm + OFF_BO))[t] = bo[t];
    __syncthreads();

    const uint32_t smb = [&]{ uint32_t a;
        asm("{ .reg .u64 t; cvta.to.shared.u64 t, %1; cvt.u32.u64 %0, t; }"
            : "=r"(a) : "l"(sm)); return a; }();

    const int lane = t & 31, warp = t >> 5;
    const int rg = warp & 3, ch = warp >> 2;   // ch in 0..3
    const int m0 = 32 * rg, ncol0 = 32 * ch;
    const int barid = rg + 1;
    const int ntiles = (B + 127) / 128;
    const float* bias = (const float*)(sm + OFF_BIAS);
    const float* wos  = (const float*)(sm + OFF_WO);
    const float* bos  = (const float*)(sm + OFF_BO);

    for (int tile = blockIdx.x; tile < ntiles; tile += gridDim.x) {
        int pbase = tile * 128;

        // ---- positional encoding (threads 0..127; row = t) ----
        if (ch == 0) {
            int row = m0 + lane;
            int p = pbase + row;
            __nv_bfloat16* fr = (__nv_bfloat16*)(sm + OFF_BUFA + row * PBA + 256);
            float xv0 = 0.f, xv1 = 0.f, xv2 = 0.f;
            if (p < B) { xv0 = x[3*p]; xv1 = x[3*p+1]; xv2 = x[3*p+2]; }
            fr[0] = __float2bfloat16(xv0);
            fr[1] = __float2bfloat16(xv1);
            fr[2] = __float2bfloat16(xv2);
            float s0 = sinf(xv0), c0v = cosf(xv0);
            float s1 = sinf(xv1), c1v = cosf(xv1);
            float s2 = sinf(xv2), c2v = cosf(xv2);
            #pragma unroll
            for (int b = 0; b < 10; b++) {
                int f = 3 + b*6;
                fr[f+0] = __float2bfloat16(s0);
                fr[f+1] = __float2bfloat16(s1);
                fr[f+2] = __float2bfloat16(s2);
                fr[f+3] = __float2bfloat16(c0v);
                fr[f+4] = __float2bfloat16(c1v);
                fr[f+5] = __float2bfloat16(c2v);
                float ns0 = 2.f*s0*c0v, nc0 = 2.f*c0v*c0v - 1.f;
                float ns1 = 2.f*s1*c1v, nc1 = 2.f*c1v*c1v - 1.f;
                float ns2 = 2.f*s2*c2v, nc2 = 2.f*c2v*c2v - 1.f;
                s0 = ns0; c0v = nc0; s1 = ns1; c1v = nc1; s2 = ns2; c2v = nc2;
            }
            fr[63] = __float2bfloat16(0.f);
        }
        asm volatile("bar.sync %0, 128;" :: "r"(barid) : "memory");

        float acc[2][4][4];

        // L0: feats(64) -> h0 (bufB)
        zero_acc(acc);
        gemm32x32(smb, OFF_BUFA + 256, PBA, OFF_W0, PW0, 4, acc, lane, m0, ncol0);
        epi32x32(sm, OFF_BUFB, PBB, bias + 0, acc, lane, m0, ncol0);
        asm volatile("bar.sync %0, 128;" :: "r"(barid) : "memory");

        // L1: h0 -> h1 (bufA cols 0..127)
        zero_acc(acc);
        gemm32x32(smb, OFF_BUFB, PBB, OFF_W1, PW1, 8, acc, lane, m0, ncol0);
        epi32x32(sm, OFF_BUFA, PBA, bias + 128, acc, lane, m0, ncol0);
        asm volatile("bar.sync %0, 128;" :: "r"(barid) : "memory");

        // L2: h1 -> h2 (bufB)
        zero_acc(acc);
        gemm32x32(smb, OFF_BUFA, PBA, OFF_W2, PW1, 8, acc, lane, m0, ncol0);
        epi32x32(sm, OFF_BUFB, PBB, bias + 256, acc, lane, m0, ncol0);
        asm volatile("bar.sync %0, 128;" :: "r"(barid) : "memory");

        // L3: concat[h2 (bufB, k0..127), feats (bufA cols 128.., k128..191)]
        zero_acc(acc);
        gemm32x32(smb, OFF_BUFB, PBB, OFF_W3, PW3, 8, acc, lane, m0, ncol0);
        gemm32x32(smb, OFF_BUFA + 256, PBA, OFF_W3 + 256, PW3, 4, acc, lane, m0, ncol0);
        epi32x32(sm, OFF_BUFA, PBA, bias + 384, acc, lane, m0, ncol0);
        asm volatile("bar.sync %0, 128;" :: "r"(barid) : "memory");

        // ---- output projection + Rodrigues ----
        // rg group covers rows m0..m0+31; warp ch covers rows m0+8ch..+7.
        // 4 lanes per row (k-quarters of 32), combined via shfl_xor 8,16.
        {
            int r  = m0 + 8*ch + (lane & 7);
            int kh = lane >> 3;             // 0..3, k-quarter 32*kh..+31
            const uint32_t* hr = (const uint32_t*)(sm + OFF_BUFA + r * PBA) + kh*16;
            const float* wop = wos + kh * 96;
            float r0 = 0.f, r1 = 0.f, r2 = 0.f;
            #pragma unroll 8
            for (int k2 = 0; k2 < 16; k2++) {
                uint32_t u = hr[k2];
                float h0 = __bfloat162float(*(const __nv_bfloat16*)&u);
                float h1 = __bfloat162float(*((const __nv_bfloat16*)&u + 1));
                r0 += h0 * wop[6*k2+0] + h1 * wop[6*k2+3];
                r1 += h0 * wop[6*k2+1] + h1 * wop[6*k2+4];
                r2 += h0 * wop[6*k2+2] + h1 * wop[6*k2+5];
            }
            r0 += __shfl_xor_sync(0xffffffff, r0, 8);
            r1 += __shfl_xor_sync(0xffffffff, r1, 8);
            r2 += __shfl_xor_sync(0xffffffff, r2, 8);
            r0 += __shfl_xor_sync(0xffffffff, r0, 16);
            r1 += __shfl_xor_sync(0xffffffff, r1, 16);
            r2 += __shfl_xor_sync(0xffffffff, r2, 16);
            int p = pbase + r;
            if (kh == 0 && p < B) {
                r0 += bos[0]; r1 += bos[1]; r2 += bos[2];
                float theta = sqrtf(r0*r0 + r1*r1 + r2*r2 + 1e-12f);
                float it = 1.f / theta;
                float e0 = r0*it, e1 = r1*it, e2 = r2*it;
                float cd0 = out[B + 3*p], cd1 = out[B + 3*p+1], cd2 = out[B + 3*p+2];
                float a = sqrtf(cd0*cd0 + cd1*cd1 + cd2*cd2 + 1e-12f);
                float ia = 1.f / a;
                float v0 = cd0*ia, v1 = cd1*ia, v2 = cd2*ia;
                float ct = cosf(theta), st = sinf(theta);
                float cr0 = e1*v2 - e2*v1;
                float cr1 = e2*v0 - e0*v2;
                float cr2 = e0*v1 - e1*v0;
                float dt = e0*v0 + e1*v1 + e2*v2;
                float omc = (1.f - ct) * dt;
                out[4*B + 3*p+0] = a * (ct*v0 + st*cr0 + omc*e0);
                out[4*B + 3*p+1] = a * (ct*v1 + st*cr1 + omc*e1);
                out[4*B + 3*p+2] = a * (ct*v2 + st*cr2 + omc*e2);
            }
        }
        asm volatile("bar.sync %0, 128;" :: "r"(barid) : "memory");
    }
}

// ---------------------------------------------------------------------------
extern "C" void kernel_launch(void* const* d_in, const int* in_sizes, int n_in,
                              void* d_out, int out_size)
{
    const float* x    = (const float*)d_in[0];
    const float* grid = (const float*)d_in[1];
    const float* w0   = (const float*)d_in[2];
    const float* b0   = (const float*)d_in[3];
    const float* w1   = (const float*)d_in[4];
    const float* b1   = (const float*)d_in[5];
    const float* w2   = (const float*)d_in[6];
    const float* b2   = (const float*)d_in[7];
    const float* w3   = (const float*)d_in[8];
    const float* b3   = (const float*)d_in[9];
    const float* wo   = (const float*)d_in[10];
    const float* bo   = (const float*)d_in[11];
    float* out = (float*)d_out;
    int B = in_sizes[0] / 3;

    gather_kernel<<<(B + 255) / 256, 256>>>(x, grid, out, B);

    int nsm = 148;
    cudaDeviceGetAttribute(&nsm, cudaDevAttrMultiProcessorCount, 0);
    cudaFuncSetAttribute(mlp_kernel,
                         cudaFuncAttributeMaxDynamicSharedMemorySize, SMEM_BYTES);
    mlp_kernel<<<nsm, 512, SMEM_BYTES>>>(x, w0, b0, w1, b1, w2, b2,
                                         w3, b3, wo, bo, out, B);
}